// round 12
// baseline (speedup 1.0000x reference)
#include <cuda_runtime.h>

#define HWD   21952              // 28^3
#define BSTR  2809856            // 128*HWD
#define NG    87808              // 4*HWD = 256 windows * 343
#define ATT_SCALE 0.17677669529663687f

#define LP 344                   // padded row length (16B aligned)
// dynamic smem: q,k,v [32][344] + ps [64][344] + rinv[64] + osp[343]
#define ATTN_SMEM_FLOATS (3*32*LP + 64*LP + 64 + 343)
#define ATTN_SMEM_BYTES  (ATTN_SMEM_FLOATS * 4)

// ---------------- scratch (device globals: the sanctioned workaround) ----------------
__device__ float g_qkv[384u * 87808u];     // rows 0..127 q, 128..255 k, 256..383 relu(v)
__device__ float g_attn[128u * 87808u];    // attention output, layout [C][B*spatial]
__device__ float g_yb[128u * 87808u];      // conv3d output, layout [C][B*spatial]
__device__ float g_wt[3456 * 128];         // conv weight transposed: [k = t*128+c][m]
__device__ float g_wqkv[128 * 384];        // qkv weight transposed: [k][m] (m: 0..255 qk, 256..383 v)
__device__ float g_wp[128 * 128];          // proj weight transposed: [k][m]
__device__ float g_bn[512];                // [0:128) sc1 [128:256) sh1 [256:384) sc2 [384:512) sh2

__device__ __forceinline__ float silu_f(float v) {
    return v / (1.0f + __expf(-v));
}

// ===================== BN stats on input x (B,C,H,W,D) =====================
__global__ __launch_bounds__(256) void bn_stats_in_kernel(const float* __restrict__ x,
                                                          const float* __restrict__ gamma,
                                                          const float* __restrict__ beta)
{
    int c = blockIdx.x;
    float s = 0.f, s2 = 0.f;
    for (int b = 0; b < 4; ++b) {
        const float* p = x + (size_t)b * BSTR + (size_t)c * HWD;
        for (int i = threadIdx.x; i < HWD; i += 256) {
            float v = p[i];
            s += v; s2 += v * v;
        }
    }
    __shared__ float rs[256], rq[256];
    rs[threadIdx.x] = s; rq[threadIdx.x] = s2;
    __syncthreads();
    for (int o = 128; o > 0; o >>= 1) {
        if (threadIdx.x < o) {
            rs[threadIdx.x] += rs[threadIdx.x + o];
            rq[threadIdx.x] += rq[threadIdx.x + o];
        }
        __syncthreads();
    }
    if (threadIdx.x == 0) {
        const float inv = 1.f / (4.f * (float)HWD);
        float m   = rs[0] * inv;
        float var = rq[0] * inv - m * m;
        float r   = rsqrtf(var + 1e-6f);
        float sc  = gamma[c] * r;
        g_bn[c]       = sc;
        g_bn[128 + c] = beta[c] - m * sc;
    }
}

// ===================== BN stats on conv output g_yb [C][NG] =====================
__global__ __launch_bounds__(256) void bn_stats_y_kernel(const float* __restrict__ gamma,
                                                         const float* __restrict__ beta)
{
    int c = blockIdx.x;
    const float* p = g_yb + (size_t)c * NG;
    float s = 0.f, s2 = 0.f;
    for (int i = threadIdx.x; i < NG; i += 256) {
        float v = p[i];
        s += v; s2 += v * v;
    }
    __shared__ float rs[256], rq[256];
    rs[threadIdx.x] = s; rq[threadIdx.x] = s2;
    __syncthreads();
    for (int o = 128; o > 0; o >>= 1) {
        if (threadIdx.x < o) {
            rs[threadIdx.x] += rs[threadIdx.x + o];
            rq[threadIdx.x] += rq[threadIdx.x + o];
        }
        __syncthreads();
    }
    if (threadIdx.x == 0) {
        const float inv = 1.f / (float)NG;
        float m   = rs[0] * inv;
        float var = rq[0] * inv - m * m;
        float r   = rsqrtf(var + 1e-6f);
        float sc  = gamma[c] * r;
        g_bn[256 + c] = sc;
        g_bn[384 + c] = beta[c] - m * sc;
    }
}

// ===================== weight transposes =====================
__global__ __launch_bounds__(256) void wt_kernel(const float* __restrict__ w_cl)
{
    int idx = blockIdx.x * 256 + threadIdx.x;   // 3456*128 = 442368
    if (idx < 3456 * 128) {
        int k = idx >> 7;
        int m = idx & 127;
        int t = k >> 7;
        int c = k & 127;
        g_wt[idx] = w_cl[(size_t)m * 3456 + c * 27 + t];
    }
}

__global__ __launch_bounds__(256) void wqkv_kernel(const float* __restrict__ w_qk,
                                                   const float* __restrict__ w_v)
{
    int idx = blockIdx.x * 256 + threadIdx.x;   // 128*384 = 49152
    if (idx < 128 * 384) {
        int k = idx / 384;
        int m = idx - k * 384;
        g_wqkv[idx] = (m < 256) ? w_qk[(size_t)m * 128 + k]
                                : w_v[(size_t)(m - 256) * 128 + k];
    }
}

__global__ __launch_bounds__(256) void wp_kernel(const float* __restrict__ w_proj)
{
    int idx = blockIdx.x * 256 + threadIdx.x;   // 128*128 = 16384
    if (idx < 128 * 128) {
        int k = idx >> 7;
        int m = idx & 127;
        g_wp[idx] = w_proj[(size_t)m * 128 + k];
    }
}

// ===================== QKV GEMM: [384x128] @ bn(windowed x)[128 x 87808], 128x128 tile =====================
// column n = w*343 + l ; window w = b0*64 + a*16 + b*4 + c ; spatial h = i*4+a (dilated)
__global__ __launch_bounds__(256, 2) void qkv_gemm_kernel(const float* __restrict__ x)
{
    __shared__ __align__(16) float As[16][128];
    __shared__ __align__(16) float Bs[16][128];
    __shared__ int colbase[128];
    int tid = threadIdx.x;
    int n0 = blockIdx.x * 128;
    int m0 = blockIdx.y * 128;
    if (tid < 128) {
        int n = n0 + tid;
        int w = n / 343;
        int l = n - w * 343;
        int b0 = w >> 6, rem = w & 63;
        int wa = rem >> 4, wb = (rem >> 2) & 3, wc = rem & 3;
        int i = l / 49; int r2 = l - i * 49;
        int j = r2 / 7; int kx = r2 - j * 7;
        colbase[tid] = b0 * BSTR + (i*4 + wa) * 784 + (j*4 + wb) * 28 + (kx*4 + wc);
    }
    __syncthreads();

    int ty = tid >> 4, tx = tid & 15;
    int kkb = tid >> 4, jb = (tid & 15) << 3;
    int akk0 = tid >> 5, acol0 = (tid & 31) << 2;
    int akk1 = akk0 + 8;

    float acc[8][8];
#pragma unroll
    for (int r = 0; r < 8; ++r)
#pragma unroll
        for (int c = 0; c < 8; ++c) acc[r][c] = 0.f;

    for (int k0 = 0; k0 < 128; k0 += 16) {
        *(float4*)&As[akk0][acol0] = *(const float4*)(g_wqkv + (size_t)(k0 + akk0) * 384 + m0 + acol0);
        *(float4*)&As[akk1][acol0] = *(const float4*)(g_wqkv + (size_t)(k0 + akk1) * 384 + m0 + acol0);
        int kg = k0 + kkb;
        float scv = g_bn[kg], shv = g_bn[128 + kg];
        const float* xk = x + (size_t)kg * HWD;
#pragma unroll
        for (int j = 0; j < 8; ++j)
            Bs[kkb][jb + j] = fmaf(xk[colbase[jb + j]], scv, shv);
        __syncthreads();
#pragma unroll
        for (int kk = 0; kk < 16; ++kk) {
            float4 a0 = *(const float4*)&As[kk][ty * 8];
            float4 a1 = *(const float4*)&As[kk][ty * 8 + 4];
            float4 b0 = *(const float4*)&Bs[kk][tx * 8];
            float4 b1 = *(const float4*)&Bs[kk][tx * 8 + 4];
            float av[8] = {a0.x, a0.y, a0.z, a0.w, a1.x, a1.y, a1.z, a1.w};
            float bv[8] = {b0.x, b0.y, b0.z, b0.w, b1.x, b1.y, b1.z, b1.w};
#pragma unroll
            for (int r = 0; r < 8; ++r)
#pragma unroll
                for (int c = 0; c < 8; ++c)
                    acc[r][c] = fmaf(av[r], bv[c], acc[r][c]);
        }
        __syncthreads();
    }

    bool dorelu = (m0 >= 256);
#pragma unroll
    for (int r = 0; r < 8; ++r) {
        int m = m0 + ty * 8 + r;
        float* dst = g_qkv + (size_t)m * NG + n0 + tx * 8;
        float4 o0, o1;
        o0.x = acc[r][0]; o0.y = acc[r][1]; o0.z = acc[r][2]; o0.w = acc[r][3];
        o1.x = acc[r][4]; o1.y = acc[r][5]; o1.z = acc[r][6]; o1.w = acc[r][7];
        if (dorelu) {
            o0.x = fmaxf(o0.x, 0.f); o0.y = fmaxf(o0.y, 0.f);
            o0.z = fmaxf(o0.z, 0.f); o0.w = fmaxf(o0.w, 0.f);
            o1.x = fmaxf(o1.x, 0.f); o1.y = fmaxf(o1.y, 0.f);
            o1.z = fmaxf(o1.z, 0.f); o1.w = fmaxf(o1.w, 0.f);
        }
        *(float4*)dst = o0;
        *(float4*)(dst + 4) = o1;
    }
}

// ===================== Attention: one block per (window, head), LDS.128 everywhere =====================
__global__ __launch_bounds__(256) void attn_kernel()
{
    extern __shared__ float sm[];
    float* qs   = sm;                  // [32][LP]
    float* ks   = sm + 32 * LP;
    float* vs   = sm + 64 * LP;
    float* ps   = sm + 96 * LP;        // [64][LP]
    float* rinv = sm + 160 * LP;       // [64]
    int*   osp  = (int*)(rinv + 64);   // [343]

    int tid = threadIdx.x;
    int w = blockIdx.x >> 2, h = blockIdx.x & 3;
    int b0 = w >> 6, rem = w & 63;
    int wa = rem >> 4, wb = (rem >> 2) & 3, wc = rem & 3;

    int gq = (h * 32) * NG + w * 343;
    for (int idx = tid; idx < 32 * LP; idx += 256) {
        int d = idx / LP, l = idx - d * LP;
        float qv = 0.f, kv = 0.f, vv = 0.f;
        if (l < 343) {
            int g = gq + d * NG + l;
            qv = g_qkv[g];
            kv = g_qkv[g + 128 * NG];
            vv = g_qkv[g + 256 * NG];
        }
        qs[idx] = qv; ks[idx] = kv; vs[idx] = vv;
    }
    if (tid < 64) ps[tid * LP + 343] = 0.f;   // pad col stays 0 forever
    for (int l = tid; l < 343; l += 256) {
        int i = l / 49, r2 = l - i * 49;
        int j = r2 / 7, kx = r2 - j * 7;
        osp[l] = b0 * HWD + (i*4 + wa) * 784 + (j*4 + wb) * 28 + (kx*4 + wc);
    }
    __syncthreads();

    int ty   = tid >> 4, tx  = tid & 15;   // S layout: rows ty*4.., cols tx*8..
    int lane = tid & 31, wp  = tid >> 5;   // softmax layout
    int ty32 = tid >> 3, tx8 = tid & 7;    // O layout

    for (int g = 0; g < 6; ++g) {
        int l0 = g * 64;
        int lb    = l0 + ty * 4;
        int lbase = min(lb, 340);          // 16B aligned, rows lbase..lbase+3 in-bounds
        bool rowok = (lb == lbase);

        // ---- S = scale * Q^T K : 4 rows x 8 cols per thread, 3 col passes ----
        for (int pass = 0; pass < 3; ++pass) {
            int mb    = pass * 128 + tx * 8;
            int mbase = min(mb, 336);
            bool colok = (mb == mbase);
            float accs[4][8];
#pragma unroll
            for (int r = 0; r < 4; ++r)
#pragma unroll
                for (int c = 0; c < 8; ++c) accs[r][c] = 0.f;
#pragma unroll 2
            for (int d = 0; d < 32; ++d) {
                float4 q4 = *(const float4*)&qs[d * LP + lbase];
                float4 k0v = *(const float4*)&ks[d * LP + mbase];
                float4 k1v = *(const float4*)&ks[d * LP + mbase + 4];
                float qv[4] = {q4.x, q4.y, q4.z, q4.w};
                float kv[8] = {k0v.x, k0v.y, k0v.z, k0v.w, k1v.x, k1v.y, k1v.z, k1v.w};
#pragma unroll
                for (int r = 0; r < 4; ++r)
#pragma unroll
                    for (int c = 0; c < 8; ++c)
                        accs[r][c] = fmaf(qv[r], kv[c], accs[r][c]);
            }
            if (rowok && colok) {
                if (mb + 7 < 343) {
#pragma unroll
                    for (int r = 0; r < 4; ++r) {
                        float4 s0, s1;
                        s0.x = accs[r][0]*ATT_SCALE; s0.y = accs[r][1]*ATT_SCALE;
                        s0.z = accs[r][2]*ATT_SCALE; s0.w = accs[r][3]*ATT_SCALE;
                        s1.x = accs[r][4]*ATT_SCALE; s1.y = accs[r][5]*ATT_SCALE;
                        s1.z = accs[r][6]*ATT_SCALE; s1.w = accs[r][7]*ATT_SCALE;
                        float* prow = &ps[(ty*4 + r) * LP + mb];
                        *(float4*)prow = s0;
                        *(float4*)(prow + 4) = s1;
                    }
                } else {
#pragma unroll
                    for (int r = 0; r < 4; ++r)
#pragma unroll
                        for (int c = 0; c < 8; ++c)
                            if (mb + c < 343)
                                ps[(ty*4 + r) * LP + mb + c] = accs[r][c] * ATT_SCALE;
                }
            }
        }
        __syncthreads();

        // ---- softmax per row (warp per 8 rows) ----
        for (int r8 = 0; r8 < 8; ++r8) {
            int rr = wp * 8 + r8;
            float mx = -1e30f;
            for (int m = lane; m < 343; m += 32) mx = fmaxf(mx, ps[rr * LP + m]);
#pragma unroll
            for (int o = 16; o > 0; o >>= 1) mx = fmaxf(mx, __shfl_xor_sync(0xffffffffu, mx, o));
            float s = 0.f;
            for (int m = lane; m < 343; m += 32) {
                float p = __expf(ps[rr * LP + m] - mx);
                ps[rr * LP + m] = p;
                s += p;
            }
#pragma unroll
            for (int o = 16; o > 0; o >>= 1) s += __shfl_xor_sync(0xffffffffu, s, o);
            if (lane == 0) rinv[rr] = 1.f / s;
        }
        __syncthreads();

        // ---- O = P V^T : 2 rows x 4 d per thread, vectorized over m ----
        float acco[2][4];
#pragma unroll
        for (int r = 0; r < 2; ++r)
#pragma unroll
            for (int j = 0; j < 4; ++j) acco[r][j] = 0.f;
        int rr0 = ty32 * 2;
        int d0  = tx8 * 4;
#pragma unroll 2
        for (int m = 0; m < LP; m += 4) {
            float4 p0 = *(const float4*)&ps[rr0 * LP + m];
            float4 p1 = *(const float4*)&ps[(rr0 + 1) * LP + m];
#pragma unroll
            for (int j = 0; j < 4; ++j) {
                float4 v4 = *(const float4*)&vs[(d0 + j) * LP + m];
                acco[0][j] = fmaf(p0.x, v4.x, acco[0][j]);
                acco[0][j] = fmaf(p0.y, v4.y, acco[0][j]);
                acco[0][j] = fmaf(p0.z, v4.z, acco[0][j]);
                acco[0][j] = fmaf(p0.w, v4.w, acco[0][j]);
                acco[1][j] = fmaf(p1.x, v4.x, acco[1][j]);
                acco[1][j] = fmaf(p1.y, v4.y, acco[1][j]);
                acco[1][j] = fmaf(p1.z, v4.z, acco[1][j]);
                acco[1][j] = fmaf(p1.w, v4.w, acco[1][j]);
            }
        }
#pragma unroll
        for (int r = 0; r < 2; ++r) {
            int l = l0 + rr0 + r;
            if (l < 343) {
                float ri = rinv[rr0 + r];
                int sp = osp[l];
#pragma unroll
                for (int j = 0; j < 4; ++j)
                    g_attn[(size_t)(h*32 + d0 + j) * NG + sp] = acco[r][j] * ri;
            }
        }
        __syncthreads();  // ps reused next group
    }
}

// ===================== conv3d 3x3x3 (128->128), 128x128 tile, 8x8 micro-tile =====================
__global__ __launch_bounds__(256, 2) void conv3d_kernel()
{
    __shared__ __align__(16) float As[16][128];
    __shared__ __align__(16) float Bs[16][128];
    __shared__ int shh[128], sww[128], sdd[128];

    int tid = threadIdx.x;
    int n0 = blockIdx.x * 128;

    if (tid < 128) {
        int n = n0 + tid;
        int b = n / HWD; int sp = n - b * HWD;
        int hh = sp / 784; int r2 = sp - hh * 784;
        int ww = r2 / 28;  int dd = r2 - ww * 28;
        shh[tid] = hh; sww[tid] = ww; sdd[tid] = dd;
    }
    __syncthreads();

    int ty = tid >> 4, tx = tid & 15;
    int kkb = tid >> 4;
    int jb  = (tid & 15) << 3;
    int akk0 = tid >> 5,        acol0 = (tid & 31) << 2;
    int akk1 = (tid + 256) >> 5, acol1 = acol0;

    float4 aR0, aR1;
    float  bR[8];

    {
        const int k0 = 0;
        aR0 = *(const float4*)(g_wt + (size_t)(k0 + akk0) * 128 + acol0);
        aR1 = *(const float4*)(g_wt + (size_t)(k0 + akk1) * 128 + acol1);
        int dh = -1, dw = -1, dz = -1;
        int delta = dh * 784 + dw * 28 + dz;
        const float* src = g_attn + (size_t)(0 + kkb) * NG + n0 + delta;
#pragma unroll
        for (int j = 0; j < 8; ++j) {
            int jj = jb + j;
            bool ok = (unsigned)(shh[jj] + dh) < 28u &&
                      (unsigned)(sww[jj] + dw) < 28u &&
                      (unsigned)(sdd[jj] + dz) < 28u;
            bR[j] = ok ? src[jj] : 0.f;
        }
    }

    float acc[8][8];
#pragma unroll
    for (int r = 0; r < 8; ++r)
#pragma unroll
        for (int c = 0; c < 8; ++c) acc[r][c] = 0.f;

    for (int k0 = 0; k0 < 3456; k0 += 16) {
        *(float4*)&As[akk0][acol0] = aR0;
        *(float4*)&As[akk1][acol1] = aR1;
#pragma unroll
        for (int j = 0; j < 8; j += 4) {
            float4 v; v.x = bR[j]; v.y = bR[j+1]; v.z = bR[j+2]; v.w = bR[j+3];
            *(float4*)&Bs[kkb][jb + j] = v;
        }
        __syncthreads();

        int k1 = k0 + 16;
        if (k1 < 3456) {
            aR0 = *(const float4*)(g_wt + (size_t)(k1 + akk0) * 128 + acol0);
            aR1 = *(const float4*)(g_wt + (size_t)(k1 + akk1) * 128 + acol1);
            int t  = k1 >> 7;
            int c0 = k1 & 127;
            int dh = t / 9 - 1;
            int r3 = t % 9;
            int dw = r3 / 3 - 1;
            int dz = r3 % 3 - 1;
            int delta = dh * 784 + dw * 28 + dz;
            const float* src = g_attn + (size_t)(c0 + kkb) * NG + n0 + delta;
#pragma unroll
            for (int j = 0; j < 8; ++j) {
                int jj = jb + j;
                bool ok = (unsigned)(shh[jj] + dh) < 28u &&
                          (unsigned)(sww[jj] + dw) < 28u &&
                          (unsigned)(sdd[jj] + dz) < 28u;
                bR[j] = ok ? src[jj] : 0.f;
            }
        }

#pragma unroll
        for (int kk = 0; kk < 16; ++kk) {
            float4 a0 = *(const float4*)&As[kk][ty * 8];
            float4 a1 = *(const float4*)&As[kk][ty * 8 + 4];
            float4 b0 = *(const float4*)&Bs[kk][tx * 8];
            float4 b1 = *(const float4*)&Bs[kk][tx * 8 + 4];
            float av[8] = {a0.x, a0.y, a0.z, a0.w, a1.x, a1.y, a1.z, a1.w};
            float bv[8] = {b0.x, b0.y, b0.z, b0.w, b1.x, b1.y, b1.z, b1.w};
#pragma unroll
            for (int r = 0; r < 8; ++r)
#pragma unroll
                for (int c = 0; c < 8; ++c)
                    acc[r][c] = fmaf(av[r], bv[c], acc[r][c]);
        }
        __syncthreads();
    }

#pragma unroll
    for (int r = 0; r < 8; ++r) {
        int m = ty * 8 + r;
        float* dst = g_yb + (size_t)m * NG + n0 + tx * 8;
        float4 o0, o1;
        o0.x = acc[r][0]; o0.y = acc[r][1]; o0.z = acc[r][2]; o0.w = acc[r][3];
        o1.x = acc[r][4]; o1.y = acc[r][5]; o1.z = acc[r][6]; o1.w = acc[r][7];
        *(float4*)dst = o0;
        *(float4*)(dst + 4) = o1;
    }
}

// ===================== final: out = x + w_proj @ (attn + silu(bn(yb))), 128x128 tile =====================
__global__ __launch_bounds__(256, 2) void final_kernel(const float* __restrict__ x,
                                                       float* __restrict__ out)
{
    __shared__ __align__(16) float As[16][128];
    __shared__ __align__(16) float Bs[16][128];
    int tid = threadIdx.x;
    int n0 = blockIdx.x * 128;

    int ty = tid >> 4, tx = tid & 15;
    int kkb = tid >> 4, jb = (tid & 15) << 3;
    int akk0 = tid >> 5, acol0 = (tid & 31) << 2;
    int akk1 = akk0 + 8;

    float acc[8][8];
#pragma unroll
    for (int r = 0; r < 8; ++r)
#pragma unroll
        for (int c = 0; c < 8; ++c) acc[r][c] = 0.f;

    for (int k0 = 0; k0 < 128; k0 += 16) {
        *(float4*)&As[akk0][acol0] = *(const float4*)(g_wp + (size_t)(k0 + akk0) * 128 + acol0);
        *(float4*)&As[akk1][acol0] = *(const float4*)(g_wp + (size_t)(k0 + akk1) * 128 + acol0);
        int i = k0 + kkb;
        float sc = g_bn[256 + i], sh = g_bn[384 + i];
        const float* yrow = g_yb   + (size_t)i * NG + n0 + jb;
        const float* arow = g_attn + (size_t)i * NG + n0 + jb;
        float4 ya0 = *(const float4*)yrow;
        float4 ya1 = *(const float4*)(yrow + 4);
        float4 aa0 = *(const float4*)arow;
        float4 aa1 = *(const float4*)(arow + 4);
        float4 t0, t1;
        t0.x = aa0.x + silu_f(fmaf(ya0.x, sc, sh));
        t0.y = aa0.y + silu_f(fmaf(ya0.y, sc, sh));
        t0.z = aa0.z + silu_f(fmaf(ya0.z, sc, sh));
        t0.w = aa0.w + silu_f(fmaf(ya0.w, sc, sh));
        t1.x = aa1.x + silu_f(fmaf(ya1.x, sc, sh));
        t1.y = aa1.y + silu_f(fmaf(ya1.y, sc, sh));
        t1.z = aa1.z + silu_f(fmaf(ya1.z, sc, sh));
        t1.w = aa1.w + silu_f(fmaf(ya1.w, sc, sh));
        *(float4*)&Bs[kkb][jb]     = t0;
        *(float4*)&Bs[kkb][jb + 4] = t1;
        __syncthreads();
#pragma unroll
        for (int kk = 0; kk < 16; ++kk) {
            float4 a0 = *(const float4*)&As[kk][ty * 8];
            float4 a1 = *(const float4*)&As[kk][ty * 8 + 4];
            float4 b0 = *(const float4*)&Bs[kk][tx * 8];
            float4 b1 = *(const float4*)&Bs[kk][tx * 8 + 4];
            float av[8] = {a0.x, a0.y, a0.z, a0.w, a1.x, a1.y, a1.z, a1.w};
            float bv[8] = {b0.x, b0.y, b0.z, b0.w, b1.x, b1.y, b1.z, b1.w};
#pragma unroll
            for (int r = 0; r < 8; ++r)
#pragma unroll
                for (int c = 0; c < 8; ++c)
                    acc[r][c] = fmaf(av[r], bv[c], acc[r][c]);
        }
        __syncthreads();
    }

    // batch boundary (21952) is 64-aligned; 8-col blocks (8-aligned, start mult of 8) never straddle
    int n = n0 + tx * 8;
    int b = n / HWD;
    int sp = n - b * HWD;
#pragma unroll
    for (int r = 0; r < 8; ++r) {
        int m = ty * 8 + r;
        size_t o = (size_t)b * BSTR + (size_t)m * HWD + sp;
        float4 x0 = *(const float4*)(x + o);
        float4 x1 = *(const float4*)(x + o + 4);
        float4 o0, o1;
        o0.x = x0.x + acc[r][0]; o0.y = x0.y + acc[r][1];
        o0.z = x0.z + acc[r][2]; o0.w = x0.w + acc[r][3];
        o1.x = x1.x + acc[r][4]; o1.y = x1.y + acc[r][5];
        o1.z = x1.z + acc[r][6]; o1.w = x1.w + acc[r][7];
        *(float4*)(out + o) = o0;
        *(float4*)(out + o + 4) = o1;
    }
}

// ===================== launch =====================
extern "C" void kernel_launch(void* const* d_in, const int* in_sizes, int n_in,
                              void* d_out, int out_size)
{
    const float* x      = (const float*)d_in[0];
    const float* g_in   = (const float*)d_in[1];
    const float* b_in   = (const float*)d_in[2];
    const float* w_qk   = (const float*)d_in[3];
    const float* w_v    = (const float*)d_in[4];
    const float* w_cl   = (const float*)d_in[5];
    const float* g_cl   = (const float*)d_in[6];
    const float* b_cl   = (const float*)d_in[7];
    const float* w_proj = (const float*)d_in[8];
    float* out = (float*)d_out;

    cudaFuncSetAttribute(attn_kernel, cudaFuncAttributeMaxDynamicSharedMemorySize,
                         ATTN_SMEM_BYTES);

    bn_stats_in_kernel<<<128, 256>>>(x, g_in, b_in);
    wt_kernel<<<1728, 256>>>(w_cl);
    wqkv_kernel<<<192, 256>>>(w_qk, w_v);
    wp_kernel<<<64, 256>>>(w_proj);
    qkv_gemm_kernel<<<dim3(686, 3), 256>>>(x);
    attn_kernel<<<1024, 256, ATTN_SMEM_BYTES>>>();
    conv3d_kernel<<<686, 256>>>();
    bn_stats_y_kernel<<<128, 256>>>(g_cl, b_cl);
    final_kernel<<<686, 256>>>(x, out);
}

// round 14
// speedup vs baseline: 2.4171x; 2.4171x over previous
#include <cuda_runtime.h>

#define HWD   21952              // 28^3
#define BSTR  2809856            // 128*HWD
#define NG    87808              // 4*HWD = 256 windows * 343
#define ATT_SCALE 0.17677669529663687f

// dynamic smem for attention: q,k,v [32][343] + probs [64][343] + rinv[64] + osp[343]
#define ATTN_SMEM_FLOATS (3*10976 + 64*343 + 64 + 343)
#define ATTN_SMEM_BYTES  (ATTN_SMEM_FLOATS * 4)

// ---------------- scratch (device globals: the sanctioned workaround) ----------------
__device__ float g_qkv[384u * 87808u];     // rows 0..127 q, 128..255 k, 256..383 relu(v)
__device__ float g_attn[128u * 87808u];    // attention output, layout [C][B*spatial]
__device__ float g_yb[128u * 87808u];      // conv3d output, layout [C][B*spatial]
__device__ float g_wt[3456 * 128];         // conv weight transposed: [k = t*128+c][m]
__device__ float g_wqkv[128 * 384];        // qkv weight transposed: [k][m] (m: 0..255 qk, 256..383 v)
__device__ float g_wp[128 * 128];          // proj weight transposed: [k][m]
__device__ float g_bn[512];                // [0:128) sc1 [128:256) sh1 [256:384) sc2 [384:512) sh2

__device__ __forceinline__ float silu_f(float v) {
    return v / (1.0f + __expf(-v));
}

// ===================== BN stats on input x (B,C,H,W,D) =====================
__global__ __launch_bounds__(256) void bn_stats_in_kernel(const float* __restrict__ x,
                                                          const float* __restrict__ gamma,
                                                          const float* __restrict__ beta)
{
    int c = blockIdx.x;
    float s = 0.f, s2 = 0.f;
    for (int b = 0; b < 4; ++b) {
        const float* p = x + (size_t)b * BSTR + (size_t)c * HWD;
        for (int i = threadIdx.x; i < HWD; i += 256) {
            float v = p[i];
            s += v; s2 += v * v;
        }
    }
    __shared__ float rs[256], rq[256];
    rs[threadIdx.x] = s; rq[threadIdx.x] = s2;
    __syncthreads();
    for (int o = 128; o > 0; o >>= 1) {
        if (threadIdx.x < o) {
            rs[threadIdx.x] += rs[threadIdx.x + o];
            rq[threadIdx.x] += rq[threadIdx.x + o];
        }
        __syncthreads();
    }
    if (threadIdx.x == 0) {
        const float inv = 1.f / (4.f * (float)HWD);
        float m   = rs[0] * inv;
        float var = rq[0] * inv - m * m;
        float r   = rsqrtf(var + 1e-6f);
        float sc  = gamma[c] * r;
        g_bn[c]       = sc;
        g_bn[128 + c] = beta[c] - m * sc;
    }
}

// ===================== BN stats on conv output g_yb [C][NG] =====================
__global__ __launch_bounds__(256) void bn_stats_y_kernel(const float* __restrict__ gamma,
                                                         const float* __restrict__ beta)
{
    int c = blockIdx.x;
    const float* p = g_yb + (size_t)c * NG;
    float s = 0.f, s2 = 0.f;
    for (int i = threadIdx.x; i < NG; i += 256) {
        float v = p[i];
        s += v; s2 += v * v;
    }
    __shared__ float rs[256], rq[256];
    rs[threadIdx.x] = s; rq[threadIdx.x] = s2;
    __syncthreads();
    for (int o = 128; o > 0; o >>= 1) {
        if (threadIdx.x < o) {
            rs[threadIdx.x] += rs[threadIdx.x + o];
            rq[threadIdx.x] += rq[threadIdx.x + o];
        }
        __syncthreads();
    }
    if (threadIdx.x == 0) {
        const float inv = 1.f / (float)NG;
        float m   = rs[0] * inv;
        float var = rq[0] * inv - m * m;
        float r   = rsqrtf(var + 1e-6f);
        float sc  = gamma[c] * r;
        g_bn[256 + c] = sc;
        g_bn[384 + c] = beta[c] - m * sc;
    }
}

// ===================== weight transposes =====================
__global__ __launch_bounds__(256) void wt_kernel(const float* __restrict__ w_cl)
{
    int idx = blockIdx.x * 256 + threadIdx.x;   // 3456*128 = 442368
    if (idx < 3456 * 128) {
        int k = idx >> 7;
        int m = idx & 127;
        int t = k >> 7;
        int c = k & 127;
        g_wt[idx] = w_cl[(size_t)m * 3456 + c * 27 + t];
    }
}

__global__ __launch_bounds__(256) void wqkv_kernel(const float* __restrict__ w_qk,
                                                   const float* __restrict__ w_v)
{
    int idx = blockIdx.x * 256 + threadIdx.x;   // 128*384 = 49152
    if (idx < 128 * 384) {
        int k = idx / 384;
        int m = idx - k * 384;
        g_wqkv[idx] = (m < 256) ? w_qk[(size_t)m * 128 + k]
                                : w_v[(size_t)(m - 256) * 128 + k];
    }
}

__global__ __launch_bounds__(256) void wp_kernel(const float* __restrict__ w_proj)
{
    int idx = blockIdx.x * 256 + threadIdx.x;   // 128*128 = 16384
    if (idx < 128 * 128) {
        int k = idx >> 7;
        int m = idx & 127;
        g_wp[idx] = w_proj[(size_t)m * 128 + k];
    }
}

// ===================== QKV GEMM: [384x128] @ bn(windowed x)[128 x 87808], 128x128 tile =====================
// column n = w*343 + l ; window w = b0*64 + a*16 + b*4 + c ; spatial h = i*4+a (dilated)
__global__ __launch_bounds__(256, 2) void qkv_gemm_kernel(const float* __restrict__ x)
{
    __shared__ __align__(16) float As[16][128];
    __shared__ __align__(16) float Bs[16][128];
    __shared__ int colbase[128];
    int tid = threadIdx.x;
    int n0 = blockIdx.x * 128;
    int m0 = blockIdx.y * 128;
    if (tid < 128) {
        int n = n0 + tid;
        int w = n / 343;
        int l = n - w * 343;
        int b0 = w >> 6, rem = w & 63;
        int wa = rem >> 4, wb = (rem >> 2) & 3, wc = rem & 3;
        int i = l / 49; int r2 = l - i * 49;
        int j = r2 / 7; int kx = r2 - j * 7;
        colbase[tid] = b0 * BSTR + (i*4 + wa) * 784 + (j*4 + wb) * 28 + (kx*4 + wc);
    }
    __syncthreads();

    int ty = tid >> 4, tx = tid & 15;
    int kkb = tid >> 4, jb = (tid & 15) << 3;
    int akk0 = tid >> 5, acol0 = (tid & 31) << 2;
    int akk1 = akk0 + 8;

    float acc[8][8];
#pragma unroll
    for (int r = 0; r < 8; ++r)
#pragma unroll
        for (int c = 0; c < 8; ++c) acc[r][c] = 0.f;

    for (int k0 = 0; k0 < 128; k0 += 16) {
        *(float4*)&As[akk0][acol0] = *(const float4*)(g_wqkv + (size_t)(k0 + akk0) * 384 + m0 + acol0);
        *(float4*)&As[akk1][acol0] = *(const float4*)(g_wqkv + (size_t)(k0 + akk1) * 384 + m0 + acol0);
        int kg = k0 + kkb;
        float scv = g_bn[kg], shv = g_bn[128 + kg];
        const float* xk = x + (size_t)kg * HWD;
#pragma unroll
        for (int j = 0; j < 8; ++j)
            Bs[kkb][jb + j] = fmaf(xk[colbase[jb + j]], scv, shv);
        __syncthreads();
#pragma unroll
        for (int kk = 0; kk < 16; ++kk) {
            float4 a0 = *(const float4*)&As[kk][ty * 8];
            float4 a1 = *(const float4*)&As[kk][ty * 8 + 4];
            float4 b0 = *(const float4*)&Bs[kk][tx * 8];
            float4 b1 = *(const float4*)&Bs[kk][tx * 8 + 4];
            float av[8] = {a0.x, a0.y, a0.z, a0.w, a1.x, a1.y, a1.z, a1.w};
            float bv[8] = {b0.x, b0.y, b0.z, b0.w, b1.x, b1.y, b1.z, b1.w};
#pragma unroll
            for (int r = 0; r < 8; ++r)
#pragma unroll
                for (int c = 0; c < 8; ++c)
                    acc[r][c] = fmaf(av[r], bv[c], acc[r][c]);
        }
        __syncthreads();
    }

    bool dorelu = (m0 >= 256);
#pragma unroll
    for (int r = 0; r < 8; ++r) {
        int m = m0 + ty * 8 + r;
        float* dst = g_qkv + (size_t)m * NG + n0 + tx * 8;
        float4 o0, o1;
        o0.x = acc[r][0]; o0.y = acc[r][1]; o0.z = acc[r][2]; o0.w = acc[r][3];
        o1.x = acc[r][4]; o1.y = acc[r][5]; o1.z = acc[r][6]; o1.w = acc[r][7];
        if (dorelu) {
            o0.x = fmaxf(o0.x, 0.f); o0.y = fmaxf(o0.y, 0.f);
            o0.z = fmaxf(o0.z, 0.f); o0.w = fmaxf(o0.w, 0.f);
            o1.x = fmaxf(o1.x, 0.f); o1.y = fmaxf(o1.y, 0.f);
            o1.z = fmaxf(o1.z, 0.f); o1.w = fmaxf(o1.w, 0.f);
        }
        *(float4*)dst = o0;
        *(float4*)(dst + 4) = o1;
    }
}

// ===================== Attention: one block per (window, head) — R11 proven version =====================
// (row stride 343 is odd -> scalar per-lane access patterns are bank-conflict-free; the
//  LP=344 float4 variant has 4*LP % 32 == 0 -> 8-way conflicts. Do not re-vectorize over d.)
__global__ __launch_bounds__(256) void attn_kernel()
{
    extern __shared__ float sm[];
    float* qs   = sm;                  // [32][343]  q[d][l]
    float* ks   = sm + 10976;          // [32][343]
    float* vs   = sm + 2 * 10976;      // [32][343]
    float* ps   = sm + 3 * 10976;      // [64][343]  scores->probs for row group
    float* rinv = ps + 64 * 343;       // [64]
    int*   osp  = (int*)(rinv + 64);   // [343] output spatial offsets

    int tid = threadIdx.x;
    int w = blockIdx.x >> 2, h = blockIdx.x & 3;
    int b0 = w >> 6, rem = w & 63;
    int wa = rem >> 4, wb = (rem >> 2) & 3, wc = rem & 3;

    int gq = (h * 32) * NG + w * 343;
    for (int idx = tid; idx < 10976; idx += 256) {
        int d = idx / 343, l = idx - d * 343;
        int g = gq + d * NG + l;
        qs[idx] = g_qkv[g];
        ks[idx] = g_qkv[g + 128 * NG];
        vs[idx] = g_qkv[g + 256 * NG];
    }
    for (int l = tid; l < 343; l += 256) {
        int i = l / 49, r2 = l - i * 49;
        int j = r2 / 7, kx = r2 - j * 7;
        osp[l] = b0 * HWD + (i*4 + wa) * 784 + (j*4 + wb) * 28 + (kx*4 + wc);
    }
    __syncthreads();

    int ty   = tid >> 4, tx  = tid & 15;   // phase S layout
    int lane = tid & 31, wp  = tid >> 5;   // softmax layout
    int ty32 = tid >> 3, tx8 = tid & 7;    // phase O layout

    for (int g = 0; g < 6; ++g) {
        int l0 = g * 64;
        int lidx[4];
#pragma unroll
        for (int r = 0; r < 4; ++r) lidx[r] = min(l0 + ty*4 + r, 342);

        // ---- S = scale * Q^T K : 4 rows x 8 cols per thread, 3 col passes ----
        for (int pass = 0; pass < 3; ++pass) {
            int mc[8]; bool mok[8];
#pragma unroll
            for (int c = 0; c < 8; ++c) {
                int mr = pass*128 + tx + c*16;
                mok[c] = (mr < 343);
                mc[c] = mok[c] ? mr : 342;
            }
            float accs[4][8];
#pragma unroll
            for (int r = 0; r < 4; ++r)
#pragma unroll
                for (int c = 0; c < 8; ++c) accs[r][c] = 0.f;
#pragma unroll 4
            for (int d = 0; d < 32; ++d) {
                float qv[4], kv[8];
#pragma unroll
                for (int r = 0; r < 4; ++r) qv[r] = qs[d*343 + lidx[r]];
#pragma unroll
                for (int c = 0; c < 8; ++c) kv[c] = ks[d*343 + mc[c]];
#pragma unroll
                for (int r = 0; r < 4; ++r)
#pragma unroll
                    for (int c = 0; c < 8; ++c)
                        accs[r][c] = fmaf(qv[r], kv[c], accs[r][c]);
            }
#pragma unroll
            for (int r = 0; r < 4; ++r)
#pragma unroll
                for (int c = 0; c < 8; ++c)
                    if (mok[c]) ps[(ty*4 + r)*343 + mc[c]] = accs[r][c] * ATT_SCALE;
        }
        __syncthreads();

        // ---- softmax per row (warp per 8 rows) ----
        for (int r8 = 0; r8 < 8; ++r8) {
            int rr = wp * 8 + r8;
            float mx = -1e30f;
            for (int m = lane; m < 343; m += 32) mx = fmaxf(mx, ps[rr*343 + m]);
#pragma unroll
            for (int o = 16; o > 0; o >>= 1) mx = fmaxf(mx, __shfl_xor_sync(0xffffffffu, mx, o));
            float s = 0.f;
            for (int m = lane; m < 343; m += 32) {
                float p = __expf(ps[rr*343 + m] - mx);
                ps[rr*343 + m] = p;
                s += p;
            }
#pragma unroll
            for (int o = 16; o > 0; o >>= 1) s += __shfl_xor_sync(0xffffffffu, s, o);
            if (lane == 0) rinv[rr] = 1.f / s;
        }
        __syncthreads();

        // ---- O = P V^T : 2 rows x 4 d per thread ----
        float acco[2][4];
#pragma unroll
        for (int r = 0; r < 2; ++r)
#pragma unroll
            for (int j = 0; j < 4; ++j) acco[r][j] = 0.f;
        int rr0 = ty32 * 2;
        int d0  = tx8 * 4;
#pragma unroll 2
        for (int m = 0; m < 343; ++m) {
            float p0 = ps[rr0*343 + m];
            float p1 = ps[(rr0+1)*343 + m];
            float vv[4];
#pragma unroll
            for (int j = 0; j < 4; ++j) vv[j] = vs[(d0 + j)*343 + m];
#pragma unroll
            for (int j = 0; j < 4; ++j) {
                acco[0][j] = fmaf(p0, vv[j], acco[0][j]);
                acco[1][j] = fmaf(p1, vv[j], acco[1][j]);
            }
        }
#pragma unroll
        for (int r = 0; r < 2; ++r) {
            int l = l0 + rr0 + r;
            if (l < 343) {
                float ri = rinv[rr0 + r];
                int sp = osp[l];
#pragma unroll
                for (int j = 0; j < 4; ++j)
                    g_attn[(size_t)(h*32 + d0 + j) * NG + sp] = acco[r][j] * ri;
            }
        }
        __syncthreads();  // ps reused next group
    }
}

// ===================== conv3d 3x3x3 (128->128), 128x128 tile, 8x8 micro-tile =====================
__global__ __launch_bounds__(256, 2) void conv3d_kernel()
{
    __shared__ __align__(16) float As[16][128];
    __shared__ __align__(16) float Bs[16][128];
    __shared__ int shh[128], sww[128], sdd[128];

    int tid = threadIdx.x;
    int n0 = blockIdx.x * 128;

    if (tid < 128) {
        int n = n0 + tid;
        int b = n / HWD; int sp = n - b * HWD;
        int hh = sp / 784; int r2 = sp - hh * 784;
        int ww = r2 / 28;  int dd = r2 - ww * 28;
        shh[tid] = hh; sww[tid] = ww; sdd[tid] = dd;
    }
    __syncthreads();

    int ty = tid >> 4, tx = tid & 15;
    int kkb = tid >> 4;
    int jb  = (tid & 15) << 3;
    int akk0 = tid >> 5,        acol0 = (tid & 31) << 2;
    int akk1 = (tid + 256) >> 5, acol1 = acol0;

    float4 aR0, aR1;
    float  bR[8];

    {
        const int k0 = 0;
        aR0 = *(const float4*)(g_wt + (size_t)(k0 + akk0) * 128 + acol0);
        aR1 = *(const float4*)(g_wt + (size_t)(k0 + akk1) * 128 + acol1);
        int dh = -1, dw = -1, dz = -1;
        int delta = dh * 784 + dw * 28 + dz;
        const float* src = g_attn + (size_t)(0 + kkb) * NG + n0 + delta;
#pragma unroll
        for (int j = 0; j < 8; ++j) {
            int jj = jb + j;
            bool ok = (unsigned)(shh[jj] + dh) < 28u &&
                      (unsigned)(sww[jj] + dw) < 28u &&
                      (unsigned)(sdd[jj] + dz) < 28u;
            bR[j] = ok ? src[jj] : 0.f;
        }
    }

    float acc[8][8];
#pragma unroll
    for (int r = 0; r < 8; ++r)
#pragma unroll
        for (int c = 0; c < 8; ++c) acc[r][c] = 0.f;

    for (int k0 = 0; k0 < 3456; k0 += 16) {
        *(float4*)&As[akk0][acol0] = aR0;
        *(float4*)&As[akk1][acol1] = aR1;
#pragma unroll
        for (int j = 0; j < 8; j += 4) {
            float4 v; v.x = bR[j]; v.y = bR[j+1]; v.z = bR[j+2]; v.w = bR[j+3];
            *(float4*)&Bs[kkb][jb + j] = v;
        }
        __syncthreads();

        int k1 = k0 + 16;
        if (k1 < 3456) {
            aR0 = *(const float4*)(g_wt + (size_t)(k1 + akk0) * 128 + acol0);
            aR1 = *(const float4*)(g_wt + (size_t)(k1 + akk1) * 128 + acol1);
            int t  = k1 >> 7;
            int c0 = k1 & 127;
            int dh = t / 9 - 1;
            int r3 = t % 9;
            int dw = r3 / 3 - 1;
            int dz = r3 % 3 - 1;
            int delta = dh * 784 + dw * 28 + dz;
            const float* src = g_attn + (size_t)(c0 + kkb) * NG + n0 + delta;
#pragma unroll
            for (int j = 0; j < 8; ++j) {
                int jj = jb + j;
                bool ok = (unsigned)(shh[jj] + dh) < 28u &&
                          (unsigned)(sww[jj] + dw) < 28u &&
                          (unsigned)(sdd[jj] + dz) < 28u;
                bR[j] = ok ? src[jj] : 0.f;
            }
        }

#pragma unroll
        for (int kk = 0; kk < 16; ++kk) {
            float4 a0 = *(const float4*)&As[kk][ty * 8];
            float4 a1 = *(const float4*)&As[kk][ty * 8 + 4];
            float4 b0 = *(const float4*)&Bs[kk][tx * 8];
            float4 b1 = *(const float4*)&Bs[kk][tx * 8 + 4];
            float av[8] = {a0.x, a0.y, a0.z, a0.w, a1.x, a1.y, a1.z, a1.w};
            float bv[8] = {b0.x, b0.y, b0.z, b0.w, b1.x, b1.y, b1.z, b1.w};
#pragma unroll
            for (int r = 0; r < 8; ++r)
#pragma unroll
                for (int c = 0; c < 8; ++c)
                    acc[r][c] = fmaf(av[r], bv[c], acc[r][c]);
        }
        __syncthreads();
    }

#pragma unroll
    for (int r = 0; r < 8; ++r) {
        int m = ty * 8 + r;
        float* dst = g_yb + (size_t)m * NG + n0 + tx * 8;
        float4 o0, o1;
        o0.x = acc[r][0]; o0.y = acc[r][1]; o0.z = acc[r][2]; o0.w = acc[r][3];
        o1.x = acc[r][4]; o1.y = acc[r][5]; o1.z = acc[r][6]; o1.w = acc[r][7];
        *(float4*)dst = o0;
        *(float4*)(dst + 4) = o1;
    }
}

// ===================== final: out = x + w_proj @ (attn + silu(bn(yb))), 128x128 tile =====================
__global__ __launch_bounds__(256, 2) void final_kernel(const float* __restrict__ x,
                                                       float* __restrict__ out)
{
    __shared__ __align__(16) float As[16][128];
    __shared__ __align__(16) float Bs[16][128];
    int tid = threadIdx.x;
    int n0 = blockIdx.x * 128;

    int ty = tid >> 4, tx = tid & 15;
    int kkb = tid >> 4, jb = (tid & 15) << 3;
    int akk0 = tid >> 5, acol0 = (tid & 31) << 2;
    int akk1 = akk0 + 8;

    float acc[8][8];
#pragma unroll
    for (int r = 0; r < 8; ++r)
#pragma unroll
        for (int c = 0; c < 8; ++c) acc[r][c] = 0.f;

    for (int k0 = 0; k0 < 128; k0 += 16) {
        *(float4*)&As[akk0][acol0] = *(const float4*)(g_wp + (size_t)(k0 + akk0) * 128 + acol0);
        *(float4*)&As[akk1][acol0] = *(const float4*)(g_wp + (size_t)(k0 + akk1) * 128 + acol0);
        int i = k0 + kkb;
        float sc = g_bn[256 + i], sh = g_bn[384 + i];
        const float* yrow = g_yb   + (size_t)i * NG + n0 + jb;
        const float* arow = g_attn + (size_t)i * NG + n0 + jb;
        float4 ya0 = *(const float4*)yrow;
        float4 ya1 = *(const float4*)(yrow + 4);
        float4 aa0 = *(const float4*)arow;
        float4 aa1 = *(const float4*)(arow + 4);
        float4 t0, t1;
        t0.x = aa0.x + silu_f(fmaf(ya0.x, sc, sh));
        t0.y = aa0.y + silu_f(fmaf(ya0.y, sc, sh));
        t0.z = aa0.z + silu_f(fmaf(ya0.z, sc, sh));
        t0.w = aa0.w + silu_f(fmaf(ya0.w, sc, sh));
        t1.x = aa1.x + silu_f(fmaf(ya1.x, sc, sh));
        t1.y = aa1.y + silu_f(fmaf(ya1.y, sc, sh));
        t1.z = aa1.z + silu_f(fmaf(ya1.z, sc, sh));
        t1.w = aa1.w + silu_f(fmaf(ya1.w, sc, sh));
        *(float4*)&Bs[kkb][jb]     = t0;
        *(float4*)&Bs[kkb][jb + 4] = t1;
        __syncthreads();
#pragma unroll
        for (int kk = 0; kk < 16; ++kk) {
            float4 a0 = *(const float4*)&As[kk][ty * 8];
            float4 a1 = *(const float4*)&As[kk][ty * 8 + 4];
            float4 b0 = *(const float4*)&Bs[kk][tx * 8];
            float4 b1 = *(const float4*)&Bs[kk][tx * 8 + 4];
            float av[8] = {a0.x, a0.y, a0.z, a0.w, a1.x, a1.y, a1.z, a1.w};
            float bv[8] = {b0.x, b0.y, b0.z, b0.w, b1.x, b1.y, b1.z, b1.w};
#pragma unroll
            for (int r = 0; r < 8; ++r)
#pragma unroll
                for (int c = 0; c < 8; ++c)
                    acc[r][c] = fmaf(av[r], bv[c], acc[r][c]);
        }
        __syncthreads();
    }

    // batch boundary (21952) is 64-aligned; 8-col blocks never straddle
    int n = n0 + tx * 8;
    int b = n / HWD;
    int sp = n - b * HWD;
#pragma unroll
    for (int r = 0; r < 8; ++r) {
        int m = ty * 8 + r;
        size_t o = (size_t)b * BSTR + (size_t)m * HWD + sp;
        float4 x0 = *(const float4*)(x + o);
        float4 x1 = *(const float4*)(x + o + 4);
        float4 o0, o1;
        o0.x = x0.x + acc[r][0]; o0.y = x0.y + acc[r][1];
        o0.z = x0.z + acc[r][2]; o0.w = x0.w + acc[r][3];
        o1.x = x1.x + acc[r][4]; o1.y = x1.y + acc[r][5];
        o1.z = x1.z + acc[r][6]; o1.w = x1.w + acc[r][7];
        *(float4*)(out + o) = o0;
        *(float4*)(out + o + 4) = o1;
    }
}

// ===================== launch =====================
extern "C" void kernel_launch(void* const* d_in, const int* in_sizes, int n_in,
                              void* d_out, int out_size)
{
    const float* x      = (const float*)d_in[0];
    const float* g_in   = (const float*)d_in[1];
    const float* b_in   = (const float*)d_in[2];
    const float* w_qk   = (const float*)d_in[3];
    const float* w_v    = (const float*)d_in[4];
    const float* w_cl   = (const float*)d_in[5];
    const float* g_cl   = (const float*)d_in[6];
    const float* b_cl   = (const float*)d_in[7];
    const float* w_proj = (const float*)d_in[8];
    float* out = (float*)d_out;

    cudaFuncSetAttribute(attn_kernel, cudaFuncAttributeMaxDynamicSharedMemorySize,
                         ATTN_SMEM_BYTES);

    bn_stats_in_kernel<<<128, 256>>>(x, g_in, b_in);
    wt_kernel<<<1728, 256>>>(w_cl);
    wqkv_kernel<<<192, 256>>>(w_qk, w_v);
    wp_kernel<<<64, 256>>>(w_proj);
    qkv_gemm_kernel<<<dim3(686, 3), 256>>>(x);
    attn_kernel<<<1024, 256, ATTN_SMEM_BYTES>>>();
    conv3d_kernel<<<686, 256>>>();
    bn_stats_y_kernel<<<128, 256>>>(g_cl, b_cl);
    final_kernel<<<686, 256>>>(x, out);
}